// round 6
// baseline (speedup 1.0000x reference)
#include <cuda_runtime.h>
#include <cstdint>

#define Bdim 32
#define Tdim 2048
#define Hdim 1024
#define Udim 1024
#define NCHUNK 16           // chunks per batch row
#define CHUNK 128           // timesteps per CTA
#define NWARP 4
#define TPW 32              // timesteps per warp
#define THREADS 128
#define PB 8                // batch rows per proj tile

// Scratch (no allocs allowed)
__device__ float g_v[Bdim * Hdim];
__device__ float g_pm[Bdim * NCHUNK];
__device__ float g_pl[Bdim * NCHUNK];
__device__ float g_pctx[(size_t)Bdim * NCHUNK * Hdim];  // 2 MB
__device__ int   g_mode;   // 0=int32 1=float32 2=uint8

__device__ __forceinline__ void cp16(uint32_t s, const float* g) {
    asm volatile("cp.async.cg.shared.global [%0], [%1], 16;" :: "r"(s), "l"(g));
}
#define CP_COMMIT() asm volatile("cp.async.commit_group;")
#define CP_WAIT0()  asm volatile("cp.async.wait_group 0;")
#define CP_WAIT1()  asm volatile("cp.async.wait_group 1;")

// ---------------------------------------------------------------------------
// Kernel 1: v[b,h] = sum_u Wa[h,u]*dec[b,u].
// grid (Hdim/32, Bdim/PB); dec tile in smem, Wa row register-resident and
// reused across the 8 b-dots. Block (0,0) also sniffs the mask format.
// ---------------------------------------------------------------------------
__global__ __launch_bounds__(256) void proj_kernel(const float* __restrict__ Wa,
                                                   const float* __restrict__ dec,
                                                   const unsigned int* __restrict__ mw) {
    const int warp = threadIdx.x >> 5;
    const int lane = threadIdx.x & 31;
    const int btile = blockIdx.y;

    __shared__ __align__(16) float sdec[PB][Udim];   // 32 KB
    __shared__ int s_ni, s_nf;
    if (threadIdx.x == 0) { s_ni = 0; s_nf = 0; }

    {   // load dec tile (coalesced float4)
        const float4* src = reinterpret_cast<const float4*>(dec + (size_t)btile * PB * Udim);
        float4* dst = reinterpret_cast<float4*>(&sdec[0][0]);
        #pragma unroll
        for (int i = 0; i < (PB * Udim / 4) / 256; ++i)
            dst[i * 256 + threadIdx.x] = src[i * 256 + threadIdx.x];
    }
    __syncthreads();

    const int hbase = blockIdx.x * 32 + warp * 4;
    #pragma unroll
    for (int hh = 0; hh < 4; ++hh) {
        const int h = hbase + hh;
        const float* wr = Wa + (size_t)h * Udim;
        float4 wv[8];
        #pragma unroll
        for (int k = 0; k < 8; ++k)
            wv[k] = *reinterpret_cast<const float4*>(wr + k * 128 + lane * 4);
        #pragma unroll
        for (int b = 0; b < PB; ++b) {
            float s = 0.f;
            #pragma unroll
            for (int k = 0; k < 8; ++k) {
                float4 dd = *reinterpret_cast<const float4*>(&sdec[b][k * 128 + lane * 4]);
                s += wv[k].x * dd.x + wv[k].y * dd.y + wv[k].z * dd.z + wv[k].w * dd.w;
            }
            #pragma unroll
            for (int o = 16; o; o >>= 1) s += __shfl_xor_sync(0xffffffffu, s, o);
            if (lane == 0) g_v[(btile * PB + b) * Hdim + h] = s;
        }
    }

    if (blockIdx.x == 0 && blockIdx.y == 0) {   // mask format sniff
        int bi = 0, bf = 0;
        for (int i = threadIdx.x; i < (Bdim * Tdim) / 4; i += 256) {
            unsigned int x = mw[i];
            if (x > 1u) bi = 1;
            if (x != 0u && x != 0x3f800000u) bf = 1;
        }
        if (bi) atomicOr(&s_ni, 1);
        if (bf) atomicOr(&s_nf, 1);
        __syncthreads();
        if (threadIdx.x == 0)
            g_mode = (!s_ni) ? 0 : ((!s_nf) ? 1 : 2);
    }
}

// ---------------------------------------------------------------------------
// Kernel 2: warp-per-timestep fused pass, mask-skip, cp.async double-buffered.
// CHUNK=128 -> 512 CTAs -> single wave at occ 6.
// ---------------------------------------------------------------------------
__global__ __launch_bounds__(THREADS, 6) void attn_main(const float* __restrict__ enc,
                                                        const void* __restrict__ mraw) {
    const int b    = blockIdx.y;
    const int c    = blockIdx.x;
    const int tid  = threadIdx.x;
    const int w    = tid >> 5;
    const int lane = tid & 31;

    __shared__ __align__(16) float sv[Hdim];              // 4 KB
    __shared__ __align__(16) float sbuf[NWARP][2][Hdim];  // 32 KB (reused for merge)
    __shared__ float sm_[NWARP], sl_[NWARP];

    for (int i = tid; i < Hdim; i += THREADS) sv[i] = g_v[b * Hdim + i];
    __syncthreads();

    const int mode  = g_mode;
    const int tbase = c * CHUNK + w * TPW;
    const float* rowp = enc + (size_t)b * Tdim * Hdim + (size_t)tbase * Hdim;
    const int mbase = b * Tdim + tbase;

    // Active-row bitmask via ballot (lane j -> row j of this warp's 32 rows).
    bool act;
    if (mode == 0)      act = ((const int*)mraw)[mbase + lane] != 0;
    else if (mode == 1) act = ((const float*)mraw)[mbase + lane] != 0.f;
    else                act = ((const unsigned char*)mraw)[mbase + lane] != 0;
    unsigned rem = __ballot_sync(0xffffffffu, act);

    float4 ctx[8];
    #pragma unroll
    for (int k = 0; k < 8; ++k) ctx[k] = make_float4(0.f, 0.f, 0.f, 0.f);
    float m = -1e30f, l = 0.f;

    const uint32_t sb0  = (uint32_t)__cvta_generic_to_shared(&sbuf[w][0][0]);
    const uint32_t sb1  = (uint32_t)__cvta_generic_to_shared(&sbuf[w][1][0]);
    const uint32_t loff = lane * 16;

    int jcur = -1;
    if (rem) {
        jcur = __ffs(rem) - 1; rem &= rem - 1;
        const float* gp = rowp + (size_t)jcur * Hdim;
        #pragma unroll
        for (int k = 0; k < 8; ++k) cp16(sb0 + k * 512 + loff, gp + k * 128 + lane * 4);
        CP_COMMIT();
    }
    int pb = 0;
    while (jcur >= 0) {
        int jn = -1;
        if (rem) {
            jn = __ffs(rem) - 1; rem &= rem - 1;
            const uint32_t dst = pb ? sb0 : sb1;
            const float* gp = rowp + (size_t)jn * Hdim;
            #pragma unroll
            for (int k = 0; k < 8; ++k) cp16(dst + k * 512 + loff, gp + k * 128 + lane * 4);
            CP_COMMIT();
            CP_WAIT1();
        } else {
            CP_WAIT0();
        }

        const float* bufc = pb ? &sbuf[w][1][0] : &sbuf[w][0][0];

        float s = 0.f;
        #pragma unroll
        for (int k = 0; k < 8; ++k) {
            float4 cu = *reinterpret_cast<const float4*>(bufc + k * 128 + lane * 4);
            float4 vv = *reinterpret_cast<const float4*>(&sv[k * 128 + lane * 4]);
            s += cu.x * vv.x + cu.y * vv.y + cu.z * vv.z + cu.w * vv.w;
        }
        #pragma unroll
        for (int o = 16; o; o >>= 1) s += __shfl_xor_sync(0xffffffffu, s, o);

        float mnew = fmaxf(m, s);
        if (mnew != m) {
            float sc = __expf(m - mnew);
            l *= sc;
            #pragma unroll
            for (int k = 0; k < 8; ++k) {
                ctx[k].x *= sc; ctx[k].y *= sc; ctx[k].z *= sc; ctx[k].w *= sc;
            }
            m = mnew;
        }
        float p = __expf(s - m);
        l += p;
        #pragma unroll
        for (int k = 0; k < 8; ++k) {
            float4 cu = *reinterpret_cast<const float4*>(bufc + k * 128 + lane * 4);
            ctx[k].x += p * cu.x; ctx[k].y += p * cu.y;
            ctx[k].z += p * cu.z; ctx[k].w += p * cu.w;
        }
        pb ^= 1;
        jcur = jn;
    }

    // ---- merge 4 warps ----
    if (lane == 0) { sm_[w] = m; sl_[w] = l; }
    float* sctxw = &sbuf[w][0][0];
    #pragma unroll
    for (int k = 0; k < 8; ++k)
        *reinterpret_cast<float4*>(sctxw + k * 128 + lane * 4) = ctx[k];
    __syncthreads();

    float M = -1e30f;
    #pragma unroll
    for (int ww = 0; ww < NWARP; ++ww) M = fmaxf(M, sm_[ww]);
    float L = 0.f, wsc[NWARP];
    #pragma unroll
    for (int ww = 0; ww < NWARP; ++ww) {
        wsc[ww] = __expf(sm_[ww] - M);
        L += sl_[ww] * wsc[ww];
    }

    const int idx = b * NCHUNK + c;
    #pragma unroll
    for (int half = 0; half < 2; ++half) {
        const int h4 = half * 512 + tid * 4;
        float4 acc = make_float4(0.f, 0.f, 0.f, 0.f);
        #pragma unroll
        for (int ww = 0; ww < NWARP; ++ww) {
            float4 pc = *reinterpret_cast<const float4*>(&sbuf[ww][0][h4]);
            acc.x += wsc[ww] * pc.x; acc.y += wsc[ww] * pc.y;
            acc.z += wsc[ww] * pc.z; acc.w += wsc[ww] * pc.w;
        }
        *reinterpret_cast<float4*>(&g_pctx[(size_t)idx * Hdim + h4]) = acc;
    }
    if (tid == 0) { g_pm[idx] = M; g_pl[idx] = L; }
}

// ---------------------------------------------------------------------------
// Kernel 3: merge NCHUNK=16 partials. grid (Bdim, 8) x 32 threads.
// ---------------------------------------------------------------------------
__global__ __launch_bounds__(32) void attn_reduce(float* __restrict__ out) {
    const int b    = blockIdx.x;
    const int lane = threadIdx.x;

    __shared__ float swgt[NCHUNK];
    __shared__ float sinv;

    float pm = (lane < NCHUNK) ? g_pm[b * NCHUNK + lane] : -1e30f;
    float pl = (lane < NCHUNK) ? g_pl[b * NCHUNK + lane] : 0.f;
    float M = pm;
    #pragma unroll
    for (int o = 16; o; o >>= 1) M = fmaxf(M, __shfl_xor_sync(0xffffffffu, M, o));
    float wg = __expf(pm - M);
    float Lc = wg * pl;
    #pragma unroll
    for (int o = 16; o; o >>= 1) Lc += __shfl_xor_sync(0xffffffffu, Lc, o);
    if (lane < NCHUNK) swgt[lane] = wg;
    if (lane == 0) sinv = (Lc > 0.f) ? 1.f / Lc : 0.f;   // all-masked row -> 0
    __syncwarp();

    const int h4 = blockIdx.y * 128 + lane * 4;
    const float* base = g_pctx + (size_t)b * NCHUNK * Hdim + h4;
    float4 acc = make_float4(0.f, 0.f, 0.f, 0.f);
    #pragma unroll
    for (int c = 0; c < NCHUNK; ++c) {
        float wgc = swgt[c];
        float4 p = *reinterpret_cast<const float4*>(base + (size_t)c * Hdim);
        acc.x += wgc * p.x; acc.y += wgc * p.y;
        acc.z += wgc * p.z; acc.w += wgc * p.w;
    }
    float inv = sinv;
    float4 o = make_float4(acc.x * inv, acc.y * inv, acc.z * inv, acc.w * inv);
    *reinterpret_cast<float4*>(&out[b * Hdim + h4]) = o;
}

// ---------------------------------------------------------------------------
extern "C" void kernel_launch(void* const* d_in, const int* in_sizes, int n_in,
                              void* d_out, int out_size) {
    const float* enc  = nullptr;   // 67108864
    const float* dec  = nullptr;   // 32768
    const void*  mask = nullptr;   // 65536
    const float* Wa   = nullptr;   // 1048576
    for (int i = 0; i < n_in; ++i) {
        switch (in_sizes[i]) {
            case 67108864: enc  = (const float*)d_in[i]; break;
            case 32768:    dec  = (const float*)d_in[i]; break;
            case 65536:    mask = d_in[i];               break;
            case 1048576:  Wa   = (const float*)d_in[i]; break;
        }
    }
    float* out = (float*)d_out;

    proj_kernel<<<dim3(Hdim / 32, Bdim / PB), 256>>>(Wa, dec, (const unsigned int*)mask);
    attn_main<<<dim3(NCHUNK, Bdim), THREADS>>>(enc, mask);
    attn_reduce<<<dim3(Bdim, 8), 32>>>(out);
}

// round 7
// speedup vs baseline: 1.0118x; 1.0118x over previous
#include <cuda_runtime.h>
#include <cstdint>

#define Bdim 32
#define Tdim 2048
#define Hdim 1024
#define Udim 1024
#define NCHUNK 16           // chunks per batch row
#define CHUNK 128           // timesteps per CTA
#define NWARP 4
#define TPW 32              // timesteps per warp
#define THREADS 128
#define PB 8                // batch rows per proj tile

// Scratch (no allocs allowed)
__device__ float g_v[Bdim * Hdim];
__device__ float g_pm[Bdim * NCHUNK];
__device__ float g_pl[Bdim * NCHUNK];
__device__ float g_pctx[(size_t)Bdim * NCHUNK * Hdim];  // 2 MB
__device__ int   g_mode;   // 0=int32 1=float32 2=uint8

__device__ __forceinline__ void cp16(uint32_t s, const float* g) {
    asm volatile("cp.async.cg.shared.global [%0], [%1], 16;" :: "r"(s), "l"(g));
}
#define CP_COMMIT() asm volatile("cp.async.commit_group;")
#define CP_WAIT0()  asm volatile("cp.async.wait_group 0;")
#define CP_WAIT1()  asm volatile("cp.async.wait_group 1;")
#define CP_WAIT2()  asm volatile("cp.async.wait_group 2;")

// ---------------------------------------------------------------------------
// Kernel 1: v[b,h] = sum_u Wa[h,u]*dec[b,u].
// grid (Hdim/32, Bdim/PB) = 128 CTAs. dec tile (8 rows, 32 KB) in smem.
// Per warp: 4 h-rows SEQUENTIALLY (unroll 1 -> one 32-reg Wa tile live at a
// time, no spill); Wa tile front-batched (MLP 8) and reused across 8 b-dots.
// Block (0,0) also sniffs the mask storage format.
// ---------------------------------------------------------------------------
__global__ __launch_bounds__(256) void proj_kernel(const float* __restrict__ Wa,
                                                   const float* __restrict__ dec,
                                                   const unsigned int* __restrict__ mw) {
    const int warp  = threadIdx.x >> 5;
    const int lane  = threadIdx.x & 31;
    const int btile = blockIdx.y;

    __shared__ __align__(16) float sdec[PB][Udim];   // 32 KB
    __shared__ int s_ni, s_nf;
    if (threadIdx.x == 0) { s_ni = 0; s_nf = 0; }

    {   // coalesced float4 load of the dec tile
        const float4* src = reinterpret_cast<const float4*>(dec + (size_t)btile * PB * Udim);
        float4* dst = reinterpret_cast<float4*>(&sdec[0][0]);
        #pragma unroll
        for (int i = 0; i < (PB * Udim / 4) / 256; ++i)
            dst[i * 256 + threadIdx.x] = src[i * 256 + threadIdx.x];
    }
    __syncthreads();

    const int hbase = blockIdx.x * 32 + warp * 4;
    #pragma unroll 1
    for (int hh = 0; hh < 4; ++hh) {
        const int h = hbase + hh;
        const float* wr = Wa + (size_t)h * Udim;
        float4 wv[8];
        #pragma unroll
        for (int k = 0; k < 8; ++k)
            wv[k] = *reinterpret_cast<const float4*>(wr + k * 128 + lane * 4);

        float s[PB];
        #pragma unroll
        for (int b = 0; b < PB; ++b) s[b] = 0.f;
        #pragma unroll
        for (int k = 0; k < 8; ++k) {
            #pragma unroll
            for (int b = 0; b < PB; ++b) {
                float4 dd = *reinterpret_cast<const float4*>(&sdec[b][k * 128 + lane * 4]);
                s[b] += wv[k].x * dd.x + wv[k].y * dd.y + wv[k].z * dd.z + wv[k].w * dd.w;
            }
        }
        #pragma unroll
        for (int b = 0; b < PB; ++b) {
            #pragma unroll
            for (int o = 16; o; o >>= 1) s[b] += __shfl_xor_sync(0xffffffffu, s[b], o);
        }
        if (lane == 0) {
            #pragma unroll
            for (int b = 0; b < PB; ++b)
                g_v[(btile * PB + b) * Hdim + h] = s[b];
        }
    }

    if (blockIdx.x == 0 && blockIdx.y == 0) {   // mask format sniff
        int bi = 0, bf = 0;
        for (int i = threadIdx.x; i < (Bdim * Tdim) / 4; i += 256) {
            unsigned int x = mw[i];
            if (x > 1u) bi = 1;
            if (x != 0u && x != 0x3f800000u) bf = 1;
        }
        if (bi) atomicOr(&s_ni, 1);
        if (bf) atomicOr(&s_nf, 1);
        __syncthreads();
        if (threadIdx.x == 0)
            g_mode = (!s_ni) ? 0 : ((!s_nf) ? 1 : 2);
    }
}

// ---------------------------------------------------------------------------
// Kernel 2: warp-per-timestep fused pass, mask-skip, 3-stage cp.async ring
// (2 rows in flight per warp while one is consumed). Warp-private buffers,
// no syncs in the main loop. 512 CTAs, occ 4 (smem 52 KB).
// ---------------------------------------------------------------------------
__global__ __launch_bounds__(THREADS, 4) void attn_main(const float* __restrict__ enc,
                                                        const void* __restrict__ mraw) {
    const int b    = blockIdx.y;
    const int c    = blockIdx.x;
    const int tid  = threadIdx.x;
    const int w    = tid >> 5;
    const int lane = tid & 31;

    __shared__ __align__(16) float sv[Hdim];              // 4 KB
    __shared__ __align__(16) float sbuf[NWARP][3][Hdim];  // 48 KB ring buffers
    __shared__ float sm_[NWARP], sl_[NWARP];

    for (int i = tid; i < Hdim; i += THREADS) sv[i] = g_v[b * Hdim + i];
    __syncthreads();

    const int mode  = g_mode;
    const int tbase = c * CHUNK + w * TPW;
    const float* rowp = enc + (size_t)b * Tdim * Hdim + (size_t)tbase * Hdim;
    const int mbase = b * Tdim + tbase;

    // lane j -> activity of row j (TPW == 32)
    bool act;
    if (mode == 0)      act = ((const int*)mraw)[mbase + lane] != 0;
    else if (mode == 1) act = ((const float*)mraw)[mbase + lane] != 0.f;
    else                act = ((const unsigned char*)mraw)[mbase + lane] != 0;
    unsigned rp = __ballot_sync(0xffffffffu, act);
    const int total = __popc(rp);

    float4 ctx[8];
    #pragma unroll
    for (int k = 0; k < 8; ++k) ctx[k] = make_float4(0.f, 0.f, 0.f, 0.f);
    float m = -1e30f, l = 0.f;

    uint32_t sb[3];
    #pragma unroll
    for (int s = 0; s < 3; ++s)
        sb[s] = (uint32_t)__cvta_generic_to_shared(&sbuf[w][s][0]);
    const uint32_t loff = lane * 16;

    // prime pipeline: up to 2 rows in flight
    int issued = 0;
    #pragma unroll
    for (int s = 0; s < 2; ++s) {
        if (issued < total) {
            int j = __ffs(rp) - 1; rp &= rp - 1;
            const float* gp = rowp + (size_t)j * Hdim;
            #pragma unroll
            for (int k = 0; k < 8; ++k) cp16(sb[s] + k * 512 + loff, gp + k * 128 + lane * 4);
            CP_COMMIT();
            ++issued;
        }
    }

    for (int i = 0; i < total; ++i) {
        if (issued < total) {
            int j = __ffs(rp) - 1; rp &= rp - 1;
            const uint32_t dst = sb[issued % 3];
            const float* gp = rowp + (size_t)j * Hdim;
            #pragma unroll
            for (int k = 0; k < 8; ++k) cp16(dst + k * 512 + loff, gp + k * 128 + lane * 4);
            CP_COMMIT();
            ++issued;
        }
        const int pend = issued - i - 1;        // warp-uniform
        if (pend >= 2)      CP_WAIT2();
        else if (pend == 1) CP_WAIT1();
        else                CP_WAIT0();

        const float* bufc = &sbuf[w][i % 3][0];

        float s = 0.f;
        #pragma unroll
        for (int k = 0; k < 8; ++k) {
            float4 cu = *reinterpret_cast<const float4*>(bufc + k * 128 + lane * 4);
            float4 vv = *reinterpret_cast<const float4*>(&sv[k * 128 + lane * 4]);
            s += cu.x * vv.x + cu.y * vv.y + cu.z * vv.z + cu.w * vv.w;
        }
        #pragma unroll
        for (int o = 16; o; o >>= 1) s += __shfl_xor_sync(0xffffffffu, s, o);

        float mnew = fmaxf(m, s);
        if (mnew != m) {
            float sc = __expf(m - mnew);   // first time: exp(-inf)=0, l/ctx are 0
            l *= sc;
            #pragma unroll
            for (int k = 0; k < 8; ++k) {
                ctx[k].x *= sc; ctx[k].y *= sc; ctx[k].z *= sc; ctx[k].w *= sc;
            }
            m = mnew;
        }
        float p = __expf(s - m);
        l += p;
        #pragma unroll
        for (int k = 0; k < 8; ++k) {
            float4 cu = *reinterpret_cast<const float4*>(bufc + k * 128 + lane * 4);
            ctx[k].x += p * cu.x; ctx[k].y += p * cu.y;
            ctx[k].z += p * cu.z; ctx[k].w += p * cu.w;
        }
    }

    // ---- merge 4 warps (reuse ring buffer 0 as per-warp ctx scratch) ----
    if (lane == 0) { sm_[w] = m; sl_[w] = l; }
    float* sctxw = &sbuf[w][0][0];
    #pragma unroll
    for (int k = 0; k < 8; ++k)
        *reinterpret_cast<float4*>(sctxw + k * 128 + lane * 4) = ctx[k];
    __syncthreads();

    float M = -1e30f;
    #pragma unroll
    for (int ww = 0; ww < NWARP; ++ww) M = fmaxf(M, sm_[ww]);
    float L = 0.f, wsc[NWARP];
    #pragma unroll
    for (int ww = 0; ww < NWARP; ++ww) {
        wsc[ww] = __expf(sm_[ww] - M);     // empty warp: exp(-1e30-M) -> 0
        L += sl_[ww] * wsc[ww];
    }

    const int idx = b * NCHUNK + c;
    #pragma unroll
    for (int half = 0; half < 2; ++half) {
        const int h4 = half * 512 + tid * 4;
        float4 acc = make_float4(0.f, 0.f, 0.f, 0.f);
        #pragma unroll
        for (int ww = 0; ww < NWARP; ++ww) {
            float4 pc = *reinterpret_cast<const float4*>(&sbuf[ww][0][h4]);
            acc.x += wsc[ww] * pc.x; acc.y += wsc[ww] * pc.y;
            acc.z += wsc[ww] * pc.z; acc.w += wsc[ww] * pc.w;
        }
        *reinterpret_cast<float4*>(&g_pctx[(size_t)idx * Hdim + h4]) = acc;
    }
    if (tid == 0) { g_pm[idx] = M; g_pl[idx] = L; }
}

// ---------------------------------------------------------------------------
// Kernel 3: merge NCHUNK=16 partials. grid (Bdim, 8) x 32 threads.
// ---------------------------------------------------------------------------
__global__ __launch_bounds__(32) void attn_reduce(float* __restrict__ out) {
    const int b    = blockIdx.x;
    const int lane = threadIdx.x;

    __shared__ float swgt[NCHUNK];
    __shared__ float sinv;

    float pm = (lane < NCHUNK) ? g_pm[b * NCHUNK + lane] : -1e30f;
    float pl = (lane < NCHUNK) ? g_pl[b * NCHUNK + lane] : 0.f;
    float M = pm;
    #pragma unroll
    for (int o = 16; o; o >>= 1) M = fmaxf(M, __shfl_xor_sync(0xffffffffu, M, o));
    float wg = __expf(pm - M);
    float Lc = wg * pl;
    #pragma unroll
    for (int o = 16; o; o >>= 1) Lc += __shfl_xor_sync(0xffffffffu, Lc, o);
    if (lane < NCHUNK) swgt[lane] = wg;
    if (lane == 0) sinv = (Lc > 0.f) ? 1.f / Lc : 0.f;   // all-masked row -> 0
    __syncwarp();

    const int h4 = blockIdx.y * 128 + lane * 4;
    const float* base = g_pctx + (size_t)b * NCHUNK * Hdim + h4;
    float4 acc = make_float4(0.f, 0.f, 0.f, 0.f);
    #pragma unroll
    for (int c = 0; c < NCHUNK; ++c) {
        float wgc = swgt[c];
        float4 p = *reinterpret_cast<const float4*>(base + (size_t)c * Hdim);
        acc.x += wgc * p.x; acc.y += wgc * p.y;
        acc.z += wgc * p.z; acc.w += wgc * p.w;
    }
    float inv = sinv;
    float4 o = make_float4(acc.x * inv, acc.y * inv, acc.z * inv, acc.w * inv);
    *reinterpret_cast<float4*>(&out[b * Hdim + h4]) = o;
}

// ---------------------------------------------------------------------------
extern "C" void kernel_launch(void* const* d_in, const int* in_sizes, int n_in,
                              void* d_out, int out_size) {
    const float* enc  = nullptr;   // 67108864
    const float* dec  = nullptr;   // 32768
    const void*  mask = nullptr;   // 65536
    const float* Wa   = nullptr;   // 1048576
    for (int i = 0; i < n_in; ++i) {
        switch (in_sizes[i]) {
            case 67108864: enc  = (const float*)d_in[i]; break;
            case 32768:    dec  = (const float*)d_in[i]; break;
            case 65536:    mask = d_in[i];               break;
            case 1048576:  Wa   = (const float*)d_in[i]; break;
        }
    }
    float* out = (float*)d_out;

    proj_kernel<<<dim3(Hdim / 32, Bdim / PB), 256>>>(Wa, dec, (const unsigned int*)mask);
    attn_main<<<dim3(NCHUNK, Bdim), THREADS>>>(enc, mask);
    attn_reduce<<<dim3(Bdim, 8), 32>>>(out);
}

// round 8
// speedup vs baseline: 1.1871x; 1.1732x over previous
#include <cuda_runtime.h>
#include <cstdint>

#define Bdim 32
#define Tdim 2048
#define Hdim 1024
#define Udim 1024
#define NCHUNK 16           // chunks per batch row
#define CHUNK 128           // timesteps per CTA
#define NWARP 4
#define THREADS 128
#define PBG 8               // batch rows per proj CTA

// Scratch (no allocs allowed)
__device__ float g_v[Bdim * Hdim];
__device__ float g_pm[Bdim * NCHUNK];
__device__ float g_pl[Bdim * NCHUNK];
__device__ float g_pctx[(size_t)Bdim * NCHUNK * Hdim];  // 2 MB
__device__ int   g_mode;   // 0=int32 1=float32 2=uint8

__device__ __forceinline__ void cp16(uint32_t s, const float* g) {
    asm volatile("cp.async.cg.shared.global [%0], [%1], 16;" :: "r"(s), "l"(g));
}
#define CP_COMMIT() asm volatile("cp.async.commit_group;")
#define CP_WAIT0()  asm volatile("cp.async.wait_group 0;")
#define CP_WAIT1()  asm volatile("cp.async.wait_group 1;")
#define CP_WAIT2()  asm volatile("cp.async.wait_group 2;")

// ---------------------------------------------------------------------------
// Kernel 1: v[b,h] = sum_u Wa[h,u]*dec[b,u].
// grid (Hdim/8, Bdim/PBG) = 512 CTAs, 256 thr. Warp owns exactly ONE h-row
// (no h-loop -> nothing to over-unroll): Wa row in 32 regs, 8 b-accumulators,
// dec tile (8 rows, 32 KB) in smem. Block (0,0) also sniffs the mask format.
// ---------------------------------------------------------------------------
__global__ __launch_bounds__(256) void proj_kernel(const float* __restrict__ Wa,
                                                   const float* __restrict__ dec,
                                                   const unsigned int* __restrict__ mw) {
    const int w    = threadIdx.x >> 5;
    const int lane = threadIdx.x & 31;
    const int b0   = blockIdx.y * PBG;
    const int h    = blockIdx.x * 8 + w;

    __shared__ __align__(16) float sdec[PBG][Udim];   // 32 KB
    __shared__ int s_ni, s_nf;
    if (threadIdx.x == 0) { s_ni = 0; s_nf = 0; }

    {   // coalesced float4 load of the dec tile
        const float4* src = reinterpret_cast<const float4*>(dec + (size_t)b0 * Udim);
        float4* dst = reinterpret_cast<float4*>(&sdec[0][0]);
        #pragma unroll
        for (int i = 0; i < (PBG * Udim / 4) / 256; ++i)
            dst[i * 256 + threadIdx.x] = src[i * 256 + threadIdx.x];
    }
    __syncthreads();

    const float* wr = Wa + (size_t)h * Udim;
    float4 wv[8];
    #pragma unroll
    for (int k = 0; k < 8; ++k)
        wv[k] = *reinterpret_cast<const float4*>(wr + k * 128 + lane * 4);

    float acc[PBG];
    #pragma unroll
    for (int b = 0; b < PBG; ++b) acc[b] = 0.f;

    #pragma unroll
    for (int k = 0; k < 8; ++k) {
        #pragma unroll
        for (int b = 0; b < PBG; ++b) {
            float4 dd = *reinterpret_cast<const float4*>(&sdec[b][k * 128 + lane * 4]);
            acc[b] += wv[k].x * dd.x + wv[k].y * dd.y + wv[k].z * dd.z + wv[k].w * dd.w;
        }
    }
    #pragma unroll
    for (int b = 0; b < PBG; ++b) {
        float s = acc[b];
        #pragma unroll
        for (int o = 16; o; o >>= 1) s += __shfl_xor_sync(0xffffffffu, s, o);
        if (lane == 0) g_v[(b0 + b) * Hdim + h] = s;
    }

    if (blockIdx.x == 0 && blockIdx.y == 0) {   // mask format sniff
        int bi = 0, bf = 0;
        for (int i = threadIdx.x; i < (Bdim * Tdim) / 4; i += 256) {
            unsigned int x = mw[i];
            if (x > 1u) bi = 1;
            if (x != 0u && x != 0x3f800000u) bf = 1;
        }
        if (bi) atomicOr(&s_ni, 1);
        if (bf) atomicOr(&s_nf, 1);
        __syncthreads();
        if (threadIdx.x == 0)
            g_mode = (!s_ni) ? 0 : ((!s_nf) ? 1 : 2);
    }
}

// ---------------------------------------------------------------------------
// Kernel 2: fused pass with CTA-level load balancing: the chunk's active rows
// are compacted into an smem list; warps consume the list strided (w, w+4, ..)
// so per-warp row counts differ by at most 1. 3-stage cp.async ring.
// ---------------------------------------------------------------------------
__global__ __launch_bounds__(THREADS, 4) void attn_main(const float* __restrict__ enc,
                                                        const void* __restrict__ mraw) {
    const int b    = blockIdx.y;
    const int c    = blockIdx.x;
    const int tid  = threadIdx.x;
    const int w    = tid >> 5;
    const int lane = tid & 31;

    __shared__ __align__(16) float sv[Hdim];              // 4 KB
    __shared__ __align__(16) float sbuf[NWARP][3][Hdim];  // 48 KB ring buffers
    __shared__ float sm_[NWARP], sl_[NWARP];
    __shared__ unsigned sflags[NWARP];
    __shared__ short slist[CHUNK];

    for (int i = tid; i < Hdim; i += THREADS) sv[i] = g_v[b * Hdim + i];

    // ---- build compacted active-row list (tid == row-in-chunk, CHUNK==128) --
    const int mode  = g_mode;
    const int tglob = b * Tdim + c * CHUNK + tid;
    bool act;
    if (mode == 0)      act = ((const int*)mraw)[tglob] != 0;
    else if (mode == 1) act = ((const float*)mraw)[tglob] != 0.f;
    else                act = ((const unsigned char*)mraw)[tglob] != 0;
    unsigned bal = __ballot_sync(0xffffffffu, act);
    if (lane == 0) sflags[w] = bal;
    __syncthreads();

    int count = 0;
    #pragma unroll
    for (int g = 0; g < NWARP; ++g) count += __popc(sflags[g]);
    if (act) {
        int pre = 0;
        #pragma unroll
        for (int g = 0; g < NWARP; ++g) if (g < w) pre += __popc(sflags[g]);
        pre += __popc(bal & ((1u << lane) - 1u));
        slist[pre] = (short)tid;
    }
    __syncthreads();

    const float* rowp = enc + (size_t)b * Tdim * Hdim + (size_t)c * CHUNK * Hdim;
    const int nit = (count > w) ? (count - w + NWARP - 1) / NWARP : 0;

    float4 ctx[8];
    #pragma unroll
    for (int k = 0; k < 8; ++k) ctx[k] = make_float4(0.f, 0.f, 0.f, 0.f);
    float m = -1e30f, l = 0.f;

    uint32_t sb[3];
    #pragma unroll
    for (int s = 0; s < 3; ++s)
        sb[s] = (uint32_t)__cvta_generic_to_shared(&sbuf[w][s][0]);
    const uint32_t loff = lane * 16;

    int issued = 0;
    #pragma unroll
    for (int s = 0; s < 2; ++s) {
        if (issued < nit) {
            const float* gp = rowp + (size_t)slist[w + NWARP * issued] * Hdim;
            #pragma unroll
            for (int k = 0; k < 8; ++k) cp16(sb[s] + k * 512 + loff, gp + k * 128 + lane * 4);
            CP_COMMIT();
            ++issued;
        }
    }

    for (int i = 0; i < nit; ++i) {
        if (issued < nit) {
            const uint32_t dst = sb[issued % 3];
            const float* gp = rowp + (size_t)slist[w + NWARP * issued] * Hdim;
            #pragma unroll
            for (int k = 0; k < 8; ++k) cp16(dst + k * 512 + loff, gp + k * 128 + lane * 4);
            CP_COMMIT();
            ++issued;
        }
        const int pend = issued - i - 1;        // warp-uniform
        if (pend >= 2)      CP_WAIT2();
        else if (pend == 1) CP_WAIT1();
        else                CP_WAIT0();

        const float* bufc = &sbuf[w][i % 3][0];

        float s = 0.f;
        #pragma unroll
        for (int k = 0; k < 8; ++k) {
            float4 cu = *reinterpret_cast<const float4*>(bufc + k * 128 + lane * 4);
            float4 vv = *reinterpret_cast<const float4*>(&sv[k * 128 + lane * 4]);
            s += cu.x * vv.x + cu.y * vv.y + cu.z * vv.z + cu.w * vv.w;
        }
        #pragma unroll
        for (int o = 16; o; o >>= 1) s += __shfl_xor_sync(0xffffffffu, s, o);

        float mnew = fmaxf(m, s);
        if (mnew != m) {
            float sc = __expf(m - mnew);   // first time: exp(-inf)=0, l/ctx are 0
            l *= sc;
            #pragma unroll
            for (int k = 0; k < 8; ++k) {
                ctx[k].x *= sc; ctx[k].y *= sc; ctx[k].z *= sc; ctx[k].w *= sc;
            }
            m = mnew;
        }
        float p = __expf(s - m);
        l += p;
        #pragma unroll
        for (int k = 0; k < 8; ++k) {
            float4 cu = *reinterpret_cast<const float4*>(bufc + k * 128 + lane * 4);
            ctx[k].x += p * cu.x; ctx[k].y += p * cu.y;
            ctx[k].z += p * cu.z; ctx[k].w += p * cu.w;
        }
    }

    // ---- merge 4 warps (reuse ring buffer 0 as per-warp ctx scratch) ----
    if (lane == 0) { sm_[w] = m; sl_[w] = l; }
    float* sctxw = &sbuf[w][0][0];
    #pragma unroll
    for (int k = 0; k < 8; ++k)
        *reinterpret_cast<float4*>(sctxw + k * 128 + lane * 4) = ctx[k];
    __syncthreads();

    float M = -1e30f;
    #pragma unroll
    for (int ww = 0; ww < NWARP; ++ww) M = fmaxf(M, sm_[ww]);
    float L = 0.f, wsc[NWARP];
    #pragma unroll
    for (int ww = 0; ww < NWARP; ++ww) {
        wsc[ww] = __expf(sm_[ww] - M);     // empty warp: exp(-1e30-M) -> 0
        L += sl_[ww] * wsc[ww];
    }

    const int idx = b * NCHUNK + c;
    #pragma unroll
    for (int half = 0; half < 2; ++half) {
        const int h4 = half * 512 + tid * 4;
        float4 acc = make_float4(0.f, 0.f, 0.f, 0.f);
        #pragma unroll
        for (int ww = 0; ww < NWARP; ++ww) {
            float4 pc = *reinterpret_cast<const float4*>(&sbuf[ww][0][h4]);
            acc.x += wsc[ww] * pc.x; acc.y += wsc[ww] * pc.y;
            acc.z += wsc[ww] * pc.z; acc.w += wsc[ww] * pc.w;
        }
        *reinterpret_cast<float4*>(&g_pctx[(size_t)idx * Hdim + h4]) = acc;
    }
    if (tid == 0) { g_pm[idx] = M; g_pl[idx] = L; }
}

// ---------------------------------------------------------------------------
// Kernel 3: merge NCHUNK=16 partials. grid (Bdim, 8) x 32 threads.
// ---------------------------------------------------------------------------
__global__ __launch_bounds__(32) void attn_reduce(float* __restrict__ out) {
    const int b    = blockIdx.x;
    const int lane = threadIdx.x;

    __shared__ float swgt[NCHUNK];
    __shared__ float sinv;

    float pm = (lane < NCHUNK) ? g_pm[b * NCHUNK + lane] : -1e30f;
    float pl = (lane < NCHUNK) ? g_pl[b * NCHUNK + lane] : 0.f;
    float M = pm;
    #pragma unroll
    for (int o = 16; o; o >>= 1) M = fmaxf(M, __shfl_xor_sync(0xffffffffu, M, o));
    float wg = __expf(pm - M);
    float Lc = wg * pl;
    #pragma unroll
    for (int o = 16; o; o >>= 1) Lc += __shfl_xor_sync(0xffffffffu, Lc, o);
    if (lane < NCHUNK) swgt[lane] = wg;
    if (lane == 0) sinv = (Lc > 0.f) ? 1.f / Lc : 0.f;   // all-masked row -> 0
    __syncwarp();

    const int h4 = blockIdx.y * 128 + lane * 4;
    const float* base = g_pctx + (size_t)b * NCHUNK * Hdim + h4;
    float4 acc = make_float4(0.f, 0.f, 0.f, 0.f);
    #pragma unroll
    for (int c = 0; c < NCHUNK; ++c) {
        float wgc = swgt[c];
        float4 p = *reinterpret_cast<const float4*>(base + (size_t)c * Hdim);
        acc.x += wgc * p.x; acc.y += wgc * p.y;
        acc.z += wgc * p.z; acc.w += wgc * p.w;
    }
    float inv = sinv;
    float4 o = make_float4(acc.x * inv, acc.y * inv, acc.z * inv, acc.w * inv);
    *reinterpret_cast<float4*>(&out[b * Hdim + h4]) = o;
}

// ---------------------------------------------------------------------------
extern "C" void kernel_launch(void* const* d_in, const int* in_sizes, int n_in,
                              void* d_out, int out_size) {
    const float* enc  = nullptr;   // 67108864
    const float* dec  = nullptr;   // 32768
    const void*  mask = nullptr;   // 65536
    const float* Wa   = nullptr;   // 1048576
    for (int i = 0; i < n_in; ++i) {
        switch (in_sizes[i]) {
            case 67108864: enc  = (const float*)d_in[i]; break;
            case 32768:    dec  = (const float*)d_in[i]; break;
            case 65536:    mask = d_in[i];               break;
            case 1048576:  Wa   = (const float*)d_in[i]; break;
        }
    }
    float* out = (float*)d_out;

    proj_kernel<<<dim3(Hdim / 8, Bdim / PBG), 256>>>(Wa, dec, (const unsigned int*)mask);
    attn_main<<<dim3(NCHUNK, Bdim), THREADS>>>(enc, mask);
    attn_reduce<<<dim3(Bdim, 8), 32>>>(out);
}

// round 9
// speedup vs baseline: 1.2454x; 1.0491x over previous
#include <cuda_runtime.h>
#include <cstdint>

#define Bdim 32
#define Tdim 2048
#define Hdim 1024
#define Udim 1024
#define NCHUNK 16           // chunks per batch row
#define CHUNK 128           // timesteps per CTA
#define NWARP 4
#define THREADS 128
#define PBG 8               // batch rows per proj CTA

// Scratch (no allocs allowed)
__device__ float g_v[Bdim * Hdim];
__device__ float g_pm[Bdim * NCHUNK];
__device__ float g_pl[Bdim * NCHUNK];
__device__ float g_pctx[(size_t)Bdim * NCHUNK * Hdim];  // 2 MB
__device__ int   g_mode;   // 0=int32 1=float32 2=uint8

__device__ __forceinline__ void cp16(uint32_t s, const float* g) {
    asm volatile("cp.async.cg.shared.global [%0], [%1], 16;" :: "r"(s), "l"(g));
}
#define CP_COMMIT() asm volatile("cp.async.commit_group;")
#define CP_WAIT0()  asm volatile("cp.async.wait_group 0;")
#define CP_WAIT1()  asm volatile("cp.async.wait_group 1;")
#define CP_WAIT2()  asm volatile("cp.async.wait_group 2;")

// ---------------------------------------------------------------------------
// Kernel 1: v[b,h] = sum_u Wa[h,u]*dec[b,u].
// grid (Hdim/16, Bdim/PBG) = 256 CTAs. Warp owns TWO h-rows (both Wa rows
// register-resident) so each sdec LDS.128 feeds 2 dots -> smem traffic halved.
// Block (0,0) also sniffs the mask storage format.
// ---------------------------------------------------------------------------
__global__ __launch_bounds__(256) void proj_kernel(const float* __restrict__ Wa,
                                                   const float* __restrict__ dec,
                                                   const unsigned int* __restrict__ mw) {
    const int w    = threadIdx.x >> 5;
    const int lane = threadIdx.x & 31;
    const int b0   = blockIdx.y * PBG;
    const int h0   = blockIdx.x * 16 + w * 2;

    __shared__ __align__(16) float sdec[PBG][Udim];   // 32 KB
    __shared__ int s_ni, s_nf;
    if (threadIdx.x == 0) { s_ni = 0; s_nf = 0; }

    {   // coalesced float4 load of the dec tile
        const float4* src = reinterpret_cast<const float4*>(dec + (size_t)b0 * Udim);
        float4* dst = reinterpret_cast<float4*>(&sdec[0][0]);
        #pragma unroll
        for (int i = 0; i < (PBG * Udim / 4) / 256; ++i)
            dst[i * 256 + threadIdx.x] = src[i * 256 + threadIdx.x];
    }
    __syncthreads();

    const float* wr0 = Wa + (size_t)h0 * Udim;
    const float* wr1 = wr0 + Udim;
    float4 wv0[8], wv1[8];
    #pragma unroll
    for (int k = 0; k < 8; ++k) {
        wv0[k] = *reinterpret_cast<const float4*>(wr0 + k * 128 + lane * 4);
        wv1[k] = *reinterpret_cast<const float4*>(wr1 + k * 128 + lane * 4);
    }

    float a0[PBG], a1[PBG];
    #pragma unroll
    for (int b = 0; b < PBG; ++b) { a0[b] = 0.f; a1[b] = 0.f; }

    #pragma unroll
    for (int k = 0; k < 8; ++k) {
        #pragma unroll
        for (int b = 0; b < PBG; ++b) {
            float4 dd = *reinterpret_cast<const float4*>(&sdec[b][k * 128 + lane * 4]);
            a0[b] += wv0[k].x * dd.x + wv0[k].y * dd.y + wv0[k].z * dd.z + wv0[k].w * dd.w;
            a1[b] += wv1[k].x * dd.x + wv1[k].y * dd.y + wv1[k].z * dd.z + wv1[k].w * dd.w;
        }
    }
    #pragma unroll
    for (int b = 0; b < PBG; ++b) {
        float s0 = a0[b], s1 = a1[b];
        #pragma unroll
        for (int o = 16; o; o >>= 1) {
            s0 += __shfl_xor_sync(0xffffffffu, s0, o);
            s1 += __shfl_xor_sync(0xffffffffu, s1, o);
        }
        if (lane == 0) {
            g_v[(b0 + b) * Hdim + h0]     = s0;
            g_v[(b0 + b) * Hdim + h0 + 1] = s1;
        }
    }

    if (blockIdx.x == 0 && blockIdx.y == 0) {   // mask format sniff
        int bi = 0, bf = 0;
        for (int i = threadIdx.x; i < (Bdim * Tdim) / 4; i += 256) {
            unsigned int x = mw[i];
            if (x > 1u) bi = 1;
            if (x != 0u && x != 0x3f800000u) bf = 1;
        }
        if (bi) atomicOr(&s_ni, 1);
        if (bf) atomicOr(&s_nf, 1);
        __syncthreads();
        if (threadIdx.x == 0)
            g_mode = (!s_ni) ? 0 : ((!s_nf) ? 1 : 2);
    }
}

// ---------------------------------------------------------------------------
// Kernel 2: fused pass. v register-resident (no sv smem, no per-row vv LDS);
// each staged row read from smem into regs ONCE (dot + ctx reuse the regs).
// CTA-level balanced row list + 3-stage cp.async ring.
// ---------------------------------------------------------------------------
__global__ __launch_bounds__(THREADS, 4) void attn_main(const float* __restrict__ enc,
                                                        const void* __restrict__ mraw) {
    const int b    = blockIdx.y;
    const int c    = blockIdx.x;
    const int tid  = threadIdx.x;
    const int w    = tid >> 5;
    const int lane = tid & 31;

    __shared__ __align__(16) float sbuf[NWARP][3][Hdim];  // 48 KB ring buffers
    __shared__ float sm_[NWARP], sl_[NWARP];
    __shared__ unsigned sflags[NWARP];
    __shared__ short slist[CHUNK];

    // v slice register-resident (same 4KB read by all 4 warps; L2-served)
    float4 vv[8];
    {
        const float* vp = g_v + (size_t)b * Hdim;
        #pragma unroll
        for (int k = 0; k < 8; ++k)
            vv[k] = *reinterpret_cast<const float4*>(vp + k * 128 + lane * 4);
    }

    // ---- build compacted active-row list (tid == row-in-chunk, CHUNK==128) --
    const int mode  = g_mode;
    const int tglob = b * Tdim + c * CHUNK + tid;
    bool act;
    if (mode == 0)      act = ((const int*)mraw)[tglob] != 0;
    else if (mode == 1) act = ((const float*)mraw)[tglob] != 0.f;
    else                act = ((const unsigned char*)mraw)[tglob] != 0;
    unsigned bal = __ballot_sync(0xffffffffu, act);
    if (lane == 0) sflags[w] = bal;
    __syncthreads();

    int count = 0;
    #pragma unroll
    for (int g = 0; g < NWARP; ++g) count += __popc(sflags[g]);
    if (act) {
        int pre = 0;
        #pragma unroll
        for (int g = 0; g < NWARP; ++g) if (g < w) pre += __popc(sflags[g]);
        pre += __popc(bal & ((1u << lane) - 1u));
        slist[pre] = (short)tid;
    }
    __syncthreads();

    const float* rowp = enc + (size_t)b * Tdim * Hdim + (size_t)c * CHUNK * Hdim;
    const int nit = (count > w) ? (count - w + NWARP - 1) / NWARP : 0;

    float4 ctx[8];
    #pragma unroll
    for (int k = 0; k < 8; ++k) ctx[k] = make_float4(0.f, 0.f, 0.f, 0.f);
    float m = -1e30f, l = 0.f;

    uint32_t sb[3];
    #pragma unroll
    for (int s = 0; s < 3; ++s)
        sb[s] = (uint32_t)__cvta_generic_to_shared(&sbuf[w][s][0]);
    const uint32_t loff = lane * 16;

    int issued = 0;
    #pragma unroll
    for (int s = 0; s < 2; ++s) {
        if (issued < nit) {
            const float* gp = rowp + (size_t)slist[w + NWARP * issued] * Hdim;
            #pragma unroll
            for (int k = 0; k < 8; ++k) cp16(sb[s] + k * 512 + loff, gp + k * 128 + lane * 4);
            CP_COMMIT();
            ++issued;
        }
    }

    for (int i = 0; i < nit; ++i) {
        if (issued < nit) {
            const uint32_t dst = sb[issued % 3];
            const float* gp = rowp + (size_t)slist[w + NWARP * issued] * Hdim;
            #pragma unroll
            for (int k = 0; k < 8; ++k) cp16(dst + k * 512 + loff, gp + k * 128 + lane * 4);
            CP_COMMIT();
            ++issued;
        }
        const int pend = issued - i - 1;        // warp-uniform
        if (pend >= 2)      CP_WAIT2();
        else if (pend == 1) CP_WAIT1();
        else                CP_WAIT0();

        const float* bufc = &sbuf[w][i % 3][0];

        // load row into registers ONCE; reused for dot and ctx accumulate
        float4 cur[8];
        #pragma unroll
        for (int k = 0; k < 8; ++k)
            cur[k] = *reinterpret_cast<const float4*>(bufc + k * 128 + lane * 4);

        float s = 0.f;
        #pragma unroll
        for (int k = 0; k < 8; ++k)
            s += cur[k].x * vv[k].x + cur[k].y * vv[k].y
               + cur[k].z * vv[k].z + cur[k].w * vv[k].w;
        #pragma unroll
        for (int o = 16; o; o >>= 1) s += __shfl_xor_sync(0xffffffffu, s, o);

        float mnew = fmaxf(m, s);
        if (mnew != m) {
            float sc = __expf(m - mnew);   // first time: exp(-inf)=0, l/ctx are 0
            l *= sc;
            #pragma unroll
            for (int k = 0; k < 8; ++k) {
                ctx[k].x *= sc; ctx[k].y *= sc; ctx[k].z *= sc; ctx[k].w *= sc;
            }
            m = mnew;
        }
        float p = __expf(s - m);
        l += p;
        #pragma unroll
        for (int k = 0; k < 8; ++k) {
            ctx[k].x += p * cur[k].x; ctx[k].y += p * cur[k].y;
            ctx[k].z += p * cur[k].z; ctx[k].w += p * cur[k].w;
        }
    }

    // ---- merge 4 warps (reuse ring buffer 0 as per-warp ctx scratch) ----
    if (lane == 0) { sm_[w] = m; sl_[w] = l; }
    float* sctxw = &sbuf[w][0][0];
    #pragma unroll
    for (int k = 0; k < 8; ++k)
        *reinterpret_cast<float4*>(sctxw + k * 128 + lane * 4) = ctx[k];
    __syncthreads();

    float M = -1e30f;
    #pragma unroll
    for (int ww = 0; ww < NWARP; ++ww) M = fmaxf(M, sm_[ww]);
    float L = 0.f, wsc[NWARP];
    #pragma unroll
    for (int ww = 0; ww < NWARP; ++ww) {
        wsc[ww] = __expf(sm_[ww] - M);     // empty warp: exp(-1e30-M) -> 0
        L += sl_[ww] * wsc[ww];
    }

    const int idx = b * NCHUNK + c;
    #pragma unroll
    for (int half = 0; half < 2; ++half) {
        const int h4 = half * 512 + tid * 4;
        float4 acc = make_float4(0.f, 0.f, 0.f, 0.f);
        #pragma unroll
        for (int ww = 0; ww < NWARP; ++ww) {
            float4 pc = *reinterpret_cast<const float4*>(&sbuf[ww][0][h4]);
            acc.x += wsc[ww] * pc.x; acc.y += wsc[ww] * pc.y;
            acc.z += wsc[ww] * pc.z; acc.w += wsc[ww] * pc.w;
        }
        *reinterpret_cast<float4*>(&g_pctx[(size_t)idx * Hdim + h4]) = acc;
    }
    if (tid == 0) { g_pm[idx] = M; g_pl[idx] = L; }
}

// ---------------------------------------------------------------------------
// Kernel 3: merge NCHUNK=16 partials. grid (Bdim, 8) x 32 threads.
// ---------------------------------------------------------------------------
__global__ __launch_bounds__(32) void attn_reduce(float* __restrict__ out) {
    const int b    = blockIdx.x;
    const int lane = threadIdx.x;

    __shared__ float swgt[NCHUNK];
    __shared__ float sinv;

    float pm = (lane < NCHUNK) ? g_pm[b * NCHUNK + lane] : -1e30f;
    float pl = (lane < NCHUNK) ? g_pl[b * NCHUNK + lane] : 0.f;
    float M = pm;
    #pragma unroll
    for (int o = 16; o; o >>= 1) M = fmaxf(M, __shfl_xor_sync(0xffffffffu, M, o));
    float wg = __expf(pm - M);
    float Lc = wg * pl;
    #pragma unroll
    for (int o = 16; o; o >>= 1) Lc += __shfl_xor_sync(0xffffffffu, Lc, o);
    if (lane < NCHUNK) swgt[lane] = wg;
    if (lane == 0) sinv = (Lc > 0.f) ? 1.f / Lc : 0.f;   // all-masked row -> 0
    __syncwarp();

    const int h4 = blockIdx.y * 128 + lane * 4;
    const float* base = g_pctx + (size_t)b * NCHUNK * Hdim + h4;
    float4 acc = make_float4(0.f, 0.f, 0.f, 0.f);
    #pragma unroll
    for (int c = 0; c < NCHUNK; ++c) {
        float wgc = swgt[c];
        float4 p = *reinterpret_cast<const float4*>(base + (size_t)c * Hdim);
        acc.x += wgc * p.x; acc.y += wgc * p.y;
        acc.z += wgc * p.z; acc.w += wgc * p.w;
    }
    float inv = sinv;
    float4 o = make_float4(acc.x * inv, acc.y * inv, acc.z * inv, acc.w * inv);
    *reinterpret_cast<float4*>(&out[b * Hdim + h4]) = o;
}

// ---------------------------------------------------------------------------
extern "C" void kernel_launch(void* const* d_in, const int* in_sizes, int n_in,
                              void* d_out, int out_size) {
    const float* enc  = nullptr;   // 67108864
    const float* dec  = nullptr;   // 32768
    const void*  mask = nullptr;   // 65536
    const float* Wa   = nullptr;   // 1048576
    for (int i = 0; i < n_in; ++i) {
        switch (in_sizes[i]) {
            case 67108864: enc  = (const float*)d_in[i]; break;
            case 32768:    dec  = (const float*)d_in[i]; break;
            case 65536:    mask = d_in[i];               break;
            case 1048576:  Wa   = (const float*)d_in[i]; break;
        }
    }
    float* out = (float*)d_out;

    proj_kernel<<<dim3(Hdim / 16, Bdim / PBG), 256>>>(Wa, dec, (const unsigned int*)mask);
    attn_main<<<dim3(NCHUNK, Bdim), THREADS>>>(enc, mask);
    attn_reduce<<<dim3(Bdim, 8), 32>>>(out);
}